// round 1
// baseline (speedup 1.0000x reference)
#include <cuda_runtime.h>
#include <stdint.h>

// ---------------------------------------------------------------------------
// Fused Instant-NGP forward:
//   x -> hash-grid encode (16 levels, T=2^19, F=2) -> density MLP 32->64->16
//   d -> dir encode (27)                             \
//   [dir(27) | h(16)] -> color MLP 43->64->64->3 -> sigmoid
// Outputs: color [N,3] then log_sigma [N], concatenated in d_out.
// One thread per point; weights staged in shared memory; matmuls fully
// unrolled so all activations stay in registers.
// ---------------------------------------------------------------------------

#define THASH 524288u
#define THASH_MASK (THASH - 1u)
#define PI2 2654435761u
#define PI3 805459861u

// shared-weight layout (floats)
#define OW1 0        // [32,64]
#define OB1 2048
#define OW2 2112     // [64,16]
#define OB2 3136
#define OW3 3152     // [43,64]
#define OB3 5904
#define OW4 5968     // [64,64]
#define OB4 10064
#define OW5 10128    // [64,3]
#define OB5 10320
#define WTOT 10323

__constant__ int c_NL[16] = {16,22,30,42,58,80,110,152,210,290,400,552,762,1052,1452,2004};

__global__ void __launch_bounds__(128)
ngp_fused_kernel(const float* __restrict__ gx, const float* __restrict__ gd,
                 const float* __restrict__ tables,
                 const float* __restrict__ w1, const float* __restrict__ b1,
                 const float* __restrict__ w2, const float* __restrict__ b2,
                 const float* __restrict__ w3, const float* __restrict__ b3,
                 const float* __restrict__ w4, const float* __restrict__ b4,
                 const float* __restrict__ w5, const float* __restrict__ b5,
                 float* __restrict__ out_color, float* __restrict__ out_sigma,
                 int N)
{
    __shared__ float sw[WTOT];
    {
        int t = threadIdx.x, bs = blockDim.x;
        for (int i = t; i < 2048; i += bs) sw[OW1 + i] = w1[i];
        for (int i = t; i < 64;   i += bs) sw[OB1 + i] = b1[i];
        for (int i = t; i < 1024; i += bs) sw[OW2 + i] = w2[i];
        for (int i = t; i < 16;   i += bs) sw[OB2 + i] = b2[i];
        for (int i = t; i < 2752; i += bs) sw[OW3 + i] = w3[i];
        for (int i = t; i < 64;   i += bs) sw[OB3 + i] = b3[i];
        for (int i = t; i < 4096; i += bs) sw[OW4 + i] = w4[i];
        for (int i = t; i < 64;   i += bs) sw[OB4 + i] = b4[i];
        for (int i = t; i < 192;  i += bs) sw[OW5 + i] = w5[i];
        for (int i = t; i < 3;    i += bs) sw[OB5 + i] = b5[i];
    }
    __syncthreads();

    int n = blockIdx.x * blockDim.x + threadIdx.x;
    if (n >= N) return;

    // ---- position, AABB mask, [0,1) coords ----
    float px = gx[3 * n + 0] * (1.0f / 3.0f);
    float py = gx[3 * n + 1] * (1.0f / 3.0f);
    float pz = gx[3 * n + 2] * (1.0f / 3.0f);
    bool mask = (fabsf(px) < 0.5f) && (fabsf(py) < 0.5f) && (fabsf(pz) < 0.5f);
    const float HI = 1.0f - 1e-7f;  // 0.99999994f
    float x0 = fminf(fmaxf(px + 0.5f, 0.0f), HI);
    float x1 = fminf(fmaxf(py + 0.5f, 0.0f), HI);
    float x2 = fminf(fmaxf(pz + 0.5f, 0.0f), HI);

    // ---- hash-grid encode: feats[32] ----
    float feats[32];
    #pragma unroll
    for (int l = 0; l < 16; l++) {
        float res = (float)c_NL[l];
        float s0 = x0 * res, s1 = x1 * res, s2 = x2 * res;
        float f0 = floorf(s0), f1 = floorf(s1), f2 = floorf(s2);
        float t0 = s0 - f0, t1 = s1 - f1, t2 = s2 - f2;
        uint32_t i0 = (uint32_t)f0, i1 = (uint32_t)f1, i2 = (uint32_t)f2;
        const float* tab = tables + (size_t)l * (size_t)THASH * 2u;
        float a0 = 0.0f, a1 = 0.0f;
        #pragma unroll
        for (int c = 0; c < 8; c++) {
            uint32_t vx = i0 + (uint32_t)(c & 1);
            uint32_t vy = i1 + (uint32_t)((c >> 1) & 1);
            uint32_t vz = i2 + (uint32_t)((c >> 2) & 1);
            uint32_t h  = vx ^ (vy * PI2) ^ (vz * PI3);
            uint32_t idx = h & THASH_MASK;
            float2 g = *reinterpret_cast<const float2*>(tab + 2u * idx);
            float w = ((c & 1)        ? t0 : 1.0f - t0)
                    * (((c >> 1) & 1) ? t1 : 1.0f - t1)
                    * (((c >> 2) & 1) ? t2 : 1.0f - t2);
            a0 = fmaf(w, g.x, a0);
            a1 = fmaf(w, g.y, a1);
        }
        feats[2 * l]     = a0;
        feats[2 * l + 1] = a1;
    }

    // ---- density MLP: 32 -> 64 (relu) -> 16 ----
    float h1[64];
    #pragma unroll
    for (int j = 0; j < 64; j++) h1[j] = sw[OB1 + j];
    #pragma unroll
    for (int k = 0; k < 32; k++) {
        float f = feats[k];
        #pragma unroll
        for (int j = 0; j < 64; j++) h1[j] = fmaf(f, sw[OW1 + k * 64 + j], h1[j]);
    }
    #pragma unroll
    for (int j = 0; j < 64; j++) h1[j] = fmaxf(h1[j], 0.0f);

    float h2[16];
    #pragma unroll
    for (int j = 0; j < 16; j++) h2[j] = sw[OB2 + j];
    #pragma unroll
    for (int k = 0; k < 64; k++) {
        float f = h1[k];
        #pragma unroll
        for (int j = 0; j < 16; j++) h2[j] = fmaf(f, sw[OW2 + k * 16 + j], h2[j]);
    }

    out_sigma[n] = mask ? h2[0] : -100000.0f;

    // ---- direction encoding: xi[43] = [d(3) | sin(12) | cos(12) | h2(16)] ----
    float xi[43];
    float dx = gd[3 * n + 0], dy = gd[3 * n + 1], dz = gd[3 * n + 2];
    xi[0] = dx; xi[1] = dy; xi[2] = dz;
    float dv[3] = {dx, dy, dz};
    #pragma unroll
    for (int dim = 0; dim < 3; dim++) {
        #pragma unroll
        for (int f = 0; f < 4; f++) {
            float ang = dv[dim] * (float)(1 << f);
            float s, c;
            sincosf(ang, &s, &c);
            xi[3  + dim * 4 + f] = s;
            xi[15 + dim * 4 + f] = c;
        }
    }
    #pragma unroll
    for (int j = 0; j < 16; j++) xi[27 + j] = h2[j];

    // ---- color MLP: 43 -> 64 (relu) -> 64 (relu) -> 3 (sigmoid) ----
    float c1[64];
    #pragma unroll
    for (int j = 0; j < 64; j++) c1[j] = sw[OB3 + j];
    #pragma unroll
    for (int k = 0; k < 43; k++) {
        float f = xi[k];
        #pragma unroll
        for (int j = 0; j < 64; j++) c1[j] = fmaf(f, sw[OW3 + k * 64 + j], c1[j]);
    }
    #pragma unroll
    for (int j = 0; j < 64; j++) c1[j] = fmaxf(c1[j], 0.0f);

    float c2[64];
    #pragma unroll
    for (int j = 0; j < 64; j++) c2[j] = sw[OB4 + j];
    #pragma unroll
    for (int k = 0; k < 64; k++) {
        float f = c1[k];
        #pragma unroll
        for (int j = 0; j < 64; j++) c2[j] = fmaf(f, sw[OW4 + k * 64 + j], c2[j]);
    }
    #pragma unroll
    for (int j = 0; j < 64; j++) c2[j] = fmaxf(c2[j], 0.0f);

    float col[3];
    #pragma unroll
    for (int j = 0; j < 3; j++) col[j] = sw[OB5 + j];
    #pragma unroll
    for (int k = 0; k < 64; k++) {
        float f = c2[k];
        #pragma unroll
        for (int j = 0; j < 3; j++) col[j] = fmaf(f, sw[OW5 + k * 3 + j], col[j]);
    }
    #pragma unroll
    for (int j = 0; j < 3; j++) {
        float v = 1.0f / (1.0f + expf(-col[j]));
        out_color[3 * n + j] = mask ? v : 0.0f;
    }
}

extern "C" void kernel_launch(void* const* d_in, const int* in_sizes, int n_in,
                              void* d_out, int out_size)
{
    const float* x      = (const float*)d_in[0];
    const float* d      = (const float*)d_in[1];
    const float* tables = (const float*)d_in[2];
    const float* w1 = (const float*)d_in[3];
    const float* b1 = (const float*)d_in[4];
    const float* w2 = (const float*)d_in[5];
    const float* b2 = (const float*)d_in[6];
    const float* w3 = (const float*)d_in[7];
    const float* b3 = (const float*)d_in[8];
    const float* w4 = (const float*)d_in[9];
    const float* b4 = (const float*)d_in[10];
    const float* w5 = (const float*)d_in[11];
    const float* b5 = (const float*)d_in[12];

    int N = in_sizes[0] / 3;
    float* out       = (float*)d_out;
    float* out_color = out;           // [N,3]
    float* out_sigma = out + 3 * (size_t)N;  // [N]

    int block = 128;
    int grid  = (N + block - 1) / block;
    ngp_fused_kernel<<<grid, block>>>(x, d, tables,
                                      w1, b1, w2, b2, w3, b3, w4, b4, w5, b5,
                                      out_color, out_sigma, N);
}

// round 2
// speedup vs baseline: 1.3701x; 1.3701x over previous
#include <cuda_runtime.h>
#include <stdint.h>

// ---------------------------------------------------------------------------
// Fused Instant-NGP forward, round 2:
//  - stream hash features directly into h1 accumulation (no feats[] array)
//  - stream dir-encoding + h2 directly into c1 accumulation (no xi[] array)
//  - c2 computed in 32-wide halves, folded immediately into col[3]
//  - all weight reads are float4 LDS.128 broadcasts
//  - __launch_bounds__(128,4) to force >=25% occupancy
//  - fast __sincosf / __expf (tolerance 1e-3, we're at 4e-8)
// ---------------------------------------------------------------------------

#define THASH 524288u
#define THASH_MASK (THASH - 1u)
#define PI2 2654435761u
#define PI3 805459861u

// shared-weight layout (floats, all offsets 16B-aligned)
#define OW1 0        // [32,64]
#define OB1 2048
#define OW2 2112     // [64,16]
#define OB2 3136
#define OW3 3152     // [43,64]
#define OB3 5904
#define OW4 5968     // [64,64]
#define OB4 10064
#define OW5 10128    // [64,3]
#define OB5 10320
#define WTOT 10324   // pad to multiple of 4

__constant__ int c_NL[16] = {16,22,30,42,58,80,110,152,210,290,400,552,762,1052,1452,2004};

__global__ void __launch_bounds__(128, 4)
ngp_fused_kernel(const float* __restrict__ gx, const float* __restrict__ gd,
                 const float* __restrict__ tables,
                 const float* __restrict__ w1, const float* __restrict__ b1,
                 const float* __restrict__ w2, const float* __restrict__ b2,
                 const float* __restrict__ w3, const float* __restrict__ b3,
                 const float* __restrict__ w4, const float* __restrict__ b4,
                 const float* __restrict__ w5, const float* __restrict__ b5,
                 float* __restrict__ out_color, float* __restrict__ out_sigma,
                 int N)
{
    __shared__ __align__(16) float sw[WTOT];
    {
        int t = threadIdx.x, bs = blockDim.x;
        for (int i = t; i < 2048; i += bs) sw[OW1 + i] = w1[i];
        for (int i = t; i < 64;   i += bs) sw[OB1 + i] = b1[i];
        for (int i = t; i < 1024; i += bs) sw[OW2 + i] = w2[i];
        for (int i = t; i < 16;   i += bs) sw[OB2 + i] = b2[i];
        for (int i = t; i < 2752; i += bs) sw[OW3 + i] = w3[i];
        for (int i = t; i < 64;   i += bs) sw[OB3 + i] = b3[i];
        for (int i = t; i < 4096; i += bs) sw[OW4 + i] = w4[i];
        for (int i = t; i < 64;   i += bs) sw[OB4 + i] = b4[i];
        for (int i = t; i < 192;  i += bs) sw[OW5 + i] = w5[i];
        for (int i = t; i < 3;    i += bs) sw[OB5 + i] = b5[i];
    }
    __syncthreads();

    int n = blockIdx.x * blockDim.x + threadIdx.x;
    if (n >= N) return;

    const float4* sw4 = reinterpret_cast<const float4*>(sw);

    // ---- position, AABB mask, [0,1) coords ----
    float px = gx[3 * n + 0] * (1.0f / 3.0f);
    float py = gx[3 * n + 1] * (1.0f / 3.0f);
    float pz = gx[3 * n + 2] * (1.0f / 3.0f);
    bool mask = (fabsf(px) < 0.5f) && (fabsf(py) < 0.5f) && (fabsf(pz) < 0.5f);
    const float HI = 1.0f - 1e-7f;
    float x0 = fminf(fmaxf(px + 0.5f, 0.0f), HI);
    float x1 = fminf(fmaxf(py + 0.5f, 0.0f), HI);
    float x2 = fminf(fmaxf(pz + 0.5f, 0.0f), HI);

    // ---- h1 = b1, then stream 16 levels of hash features straight in ----
    float h1[64];
    #pragma unroll
    for (int j4 = 0; j4 < 16; j4++) {
        float4 b = sw4[(OB1 >> 2) + j4];
        h1[4*j4+0] = b.x; h1[4*j4+1] = b.y; h1[4*j4+2] = b.z; h1[4*j4+3] = b.w;
    }

    #pragma unroll
    for (int l = 0; l < 16; l++) {
        float res = (float)c_NL[l];
        float s0 = x0 * res, s1 = x1 * res, s2 = x2 * res;
        float f0 = floorf(s0), f1 = floorf(s1), f2 = floorf(s2);
        float t0 = s0 - f0, t1 = s1 - f1, t2 = s2 - f2;
        uint32_t i0 = (uint32_t)f0, i1 = (uint32_t)f1, i2 = (uint32_t)f2;
        const float2* tab = reinterpret_cast<const float2*>(tables) + (size_t)l * (size_t)THASH;

        uint32_t hy0 = i1 * PI2,        hy1 = (i1 + 1u) * PI2;
        uint32_t hz0 = i2 * PI3,        hz1 = (i2 + 1u) * PI3;
        // 8 corner indices
        uint32_t k000 = (i0        ^ hy0 ^ hz0) & THASH_MASK;
        uint32_t k100 = ((i0 + 1u) ^ hy0 ^ hz0) & THASH_MASK;
        uint32_t k010 = (i0        ^ hy1 ^ hz0) & THASH_MASK;
        uint32_t k110 = ((i0 + 1u) ^ hy1 ^ hz0) & THASH_MASK;
        uint32_t k001 = (i0        ^ hy0 ^ hz1) & THASH_MASK;
        uint32_t k101 = ((i0 + 1u) ^ hy0 ^ hz1) & THASH_MASK;
        uint32_t k011 = (i0        ^ hy1 ^ hz1) & THASH_MASK;
        uint32_t k111 = ((i0 + 1u) ^ hy1 ^ hz1) & THASH_MASK;

        float2 g000 = __ldg(tab + k000);
        float2 g100 = __ldg(tab + k100);
        float2 g010 = __ldg(tab + k010);
        float2 g110 = __ldg(tab + k110);
        float2 g001 = __ldg(tab + k001);
        float2 g101 = __ldg(tab + k101);
        float2 g011 = __ldg(tab + k011);
        float2 g111 = __ldg(tab + k111);

        float u0 = 1.0f - t0, u1 = 1.0f - t1, u2 = 1.0f - t2;
        float w000 = u0 * u1 * u2, w100 = t0 * u1 * u2;
        float w010 = u0 * t1 * u2, w110 = t0 * t1 * u2;
        float w001 = u0 * u1 * t2, w101 = t0 * u1 * t2;
        float w011 = u0 * t1 * t2, w111 = t0 * t1 * t2;

        float a0 = w000 * g000.x + w100 * g100.x + w010 * g010.x + w110 * g110.x
                 + w001 * g001.x + w101 * g101.x + w011 * g011.x + w111 * g111.x;
        float a1 = w000 * g000.y + w100 * g100.y + w010 * g010.y + w110 * g110.y
                 + w001 * g001.y + w101 * g101.y + w011 * g011.y + w111 * g111.y;

        // h1 += a0 * w1[2l,:] + a1 * w1[2l+1,:]
        const int r0 = (OW1 + (2 * l) * 64) >> 2;
        const int r1 = (OW1 + (2 * l + 1) * 64) >> 2;
        #pragma unroll
        for (int j4 = 0; j4 < 16; j4++) {
            float4 u = sw4[r0 + j4];
            float4 v = sw4[r1 + j4];
            h1[4*j4+0] = fmaf(a0, u.x, fmaf(a1, v.x, h1[4*j4+0]));
            h1[4*j4+1] = fmaf(a0, u.y, fmaf(a1, v.y, h1[4*j4+1]));
            h1[4*j4+2] = fmaf(a0, u.z, fmaf(a1, v.z, h1[4*j4+2]));
            h1[4*j4+3] = fmaf(a0, u.w, fmaf(a1, v.w, h1[4*j4+3]));
        }
    }

    // ---- h2 = relu(h1) @ w2 + b2 ----
    float h2[16];
    #pragma unroll
    for (int j4 = 0; j4 < 4; j4++) {
        float4 b = sw4[(OB2 >> 2) + j4];
        h2[4*j4+0] = b.x; h2[4*j4+1] = b.y; h2[4*j4+2] = b.z; h2[4*j4+3] = b.w;
    }
    #pragma unroll
    for (int k = 0; k < 64; k++) {
        float f = fmaxf(h1[k], 0.0f);
        const int rb = (OW2 + k * 16) >> 2;
        #pragma unroll
        for (int j4 = 0; j4 < 4; j4++) {
            float4 u = sw4[rb + j4];
            h2[4*j4+0] = fmaf(f, u.x, h2[4*j4+0]);
            h2[4*j4+1] = fmaf(f, u.y, h2[4*j4+1]);
            h2[4*j4+2] = fmaf(f, u.z, h2[4*j4+2]);
            h2[4*j4+3] = fmaf(f, u.w, h2[4*j4+3]);
        }
    }

    out_sigma[n] = mask ? h2[0] : -100000.0f;

    // ---- c1 = relu(b3 + [dir(27)|h2(16)] @ w3), streamed (no xi array) ----
    float c1[64];
    #pragma unroll
    for (int j4 = 0; j4 < 16; j4++) {
        float4 b = sw4[(OB3 >> 2) + j4];
        c1[4*j4+0] = b.x; c1[4*j4+1] = b.y; c1[4*j4+2] = b.z; c1[4*j4+3] = b.w;
    }

    float dv[3];
    dv[0] = gd[3 * n + 0]; dv[1] = gd[3 * n + 1]; dv[2] = gd[3 * n + 2];

    // helper macro: c1 += val * w3[row,:]
    #define C1_ACC(row, val) do {                                             \
        const int _rb = (OW3 + (row) * 64) >> 2;                              \
        float _f = (val);                                                     \
        _Pragma("unroll")                                                     \
        for (int j4 = 0; j4 < 16; j4++) {                                     \
            float4 u = sw4[_rb + j4];                                         \
            c1[4*j4+0] = fmaf(_f, u.x, c1[4*j4+0]);                           \
            c1[4*j4+1] = fmaf(_f, u.y, c1[4*j4+1]);                           \
            c1[4*j4+2] = fmaf(_f, u.z, c1[4*j4+2]);                           \
            c1[4*j4+3] = fmaf(_f, u.w, c1[4*j4+3]);                           \
        }                                                                     \
    } while (0)

    C1_ACC(0, dv[0]);
    C1_ACC(1, dv[1]);
    C1_ACC(2, dv[2]);
    #pragma unroll
    for (int dim = 0; dim < 3; dim++) {
        #pragma unroll
        for (int f = 0; f < 4; f++) {
            float ang = dv[dim] * (float)(1 << f);
            float s, c;
            __sincosf(ang, &s, &c);
            C1_ACC(3  + dim * 4 + f, s);
            C1_ACC(15 + dim * 4 + f, c);
        }
    }
    #pragma unroll
    for (int j = 0; j < 16; j++) C1_ACC(27 + j, h2[j]);
    #undef C1_ACC

    #pragma unroll
    for (int j = 0; j < 64; j++) c1[j] = fmaxf(c1[j], 0.0f);

    // ---- c2 = relu(c1 @ w4 + b4) in 32-wide halves, folded into col ----
    float col[3];
    {
        float4 b0 = sw4[OB5 >> 2];  // b5[0..3], only first 3 used
        col[0] = b0.x; col[1] = b0.y; col[2] = b0.z;
    }

    #pragma unroll
    for (int half = 0; half < 2; half++) {
        float c2h[32];
        const int jbase = half * 32;
        #pragma unroll
        for (int j4 = 0; j4 < 8; j4++) {
            float4 b = sw4[((OB4 + jbase) >> 2) + j4];
            c2h[4*j4+0] = b.x; c2h[4*j4+1] = b.y; c2h[4*j4+2] = b.z; c2h[4*j4+3] = b.w;
        }
        #pragma unroll
        for (int k = 0; k < 64; k++) {
            float f = c1[k];
            const int rb = (OW4 + k * 64 + jbase) >> 2;
            #pragma unroll
            for (int j4 = 0; j4 < 8; j4++) {
                float4 u = sw4[rb + j4];
                c2h[4*j4+0] = fmaf(f, u.x, c2h[4*j4+0]);
                c2h[4*j4+1] = fmaf(f, u.y, c2h[4*j4+1]);
                c2h[4*j4+2] = fmaf(f, u.z, c2h[4*j4+2]);
                c2h[4*j4+3] = fmaf(f, u.w, c2h[4*j4+3]);
            }
        }
        #pragma unroll
        for (int k = 0; k < 32; k++) {
            float f = fmaxf(c2h[k], 0.0f);
            const int rw = OW5 + (jbase + k) * 3;
            col[0] = fmaf(f, sw[rw + 0], col[0]);
            col[1] = fmaf(f, sw[rw + 1], col[1]);
            col[2] = fmaf(f, sw[rw + 2], col[2]);
        }
    }

    #pragma unroll
    for (int j = 0; j < 3; j++) {
        float v = 1.0f / (1.0f + __expf(-col[j]));
        out_color[3 * n + j] = mask ? v : 0.0f;
    }
}

extern "C" void kernel_launch(void* const* d_in, const int* in_sizes, int n_in,
                              void* d_out, int out_size)
{
    const float* x      = (const float*)d_in[0];
    const float* d      = (const float*)d_in[1];
    const float* tables = (const float*)d_in[2];
    const float* w1 = (const float*)d_in[3];
    const float* b1 = (const float*)d_in[4];
    const float* w2 = (const float*)d_in[5];
    const float* b2 = (const float*)d_in[6];
    const float* w3 = (const float*)d_in[7];
    const float* b3 = (const float*)d_in[8];
    const float* w4 = (const float*)d_in[9];
    const float* b4 = (const float*)d_in[10];
    const float* w5 = (const float*)d_in[11];
    const float* b5 = (const float*)d_in[12];

    int N = in_sizes[0] / 3;
    float* out       = (float*)d_out;
    float* out_color = out;                   // [N,3]
    float* out_sigma = out + 3 * (size_t)N;   // [N]

    int block = 128;
    int grid  = (N + block - 1) / block;
    ngp_fused_kernel<<<grid, block>>>(x, d, tables,
                                      w1, b1, w2, b2, w3, b3, w4, b4, w5, b5,
                                      out_color, out_sigma, N);
}

// round 3
// speedup vs baseline: 1.4186x; 1.0354x over previous
#include <cuda_runtime.h>
#include <stdint.h>

// ---------------------------------------------------------------------------
// Fused Instant-NGP forward, round 3:
//  - ALL MLP weights in __constant__ memory (LDCU/uniform path, off L1tex),
//    filled per-launch by capturable cudaMemcpyToSymbolAsync D2D copies
//  - paired corner gathers: for even x, corners (x,*) and (x+1,*) are
//    adjacent hash entries -> one aligned float4 load covers both
//  - activations stay in registers; matmuls fully unrolled
// ---------------------------------------------------------------------------

#define THASH 524288u
#define THASH_MASK (THASH - 1u)
#define PI2 2654435761u
#define PI3 805459861u

// constant-weight layout (floats, 16B-aligned chunks)
#define OW1 0        // [32,64]
#define OB1 2048
#define OW2 2112     // [64,16]
#define OB2 3136
#define OW3 3152     // [43,64]
#define OB3 5904
#define OW4 5968     // [64,64]
#define OB4 10064
#define OW5 10128    // [64,3]
#define OB5 10320
#define WTOT 10324

__constant__ __align__(16) float cw[WTOT];

__global__ void __launch_bounds__(128, 4)
ngp_fused_kernel(const float* __restrict__ gx, const float* __restrict__ gd,
                 const float* __restrict__ tables,
                 float* __restrict__ out_color, float* __restrict__ out_sigma,
                 int N)
{
    const float4* cw4 = reinterpret_cast<const float4*>(cw);

    int n = blockIdx.x * blockDim.x + threadIdx.x;
    if (n >= N) return;

    // ---- position, AABB mask, [0,1) coords ----
    float px = gx[3 * n + 0] * (1.0f / 3.0f);
    float py = gx[3 * n + 1] * (1.0f / 3.0f);
    float pz = gx[3 * n + 2] * (1.0f / 3.0f);
    bool mask = (fabsf(px) < 0.5f) && (fabsf(py) < 0.5f) && (fabsf(pz) < 0.5f);
    const float HI = 1.0f - 1e-7f;
    float x0 = fminf(fmaxf(px + 0.5f, 0.0f), HI);
    float x1 = fminf(fmaxf(py + 0.5f, 0.0f), HI);
    float x2 = fminf(fmaxf(pz + 0.5f, 0.0f), HI);

    // ---- h1 = b1 + sum over levels ----
    float h1[64];
    #pragma unroll
    for (int j4 = 0; j4 < 16; j4++) {
        float4 b = cw4[(OB1 >> 2) + j4];
        h1[4*j4+0] = b.x; h1[4*j4+1] = b.y; h1[4*j4+2] = b.z; h1[4*j4+3] = b.w;
    }

    const float resf[16] = {16.f,22.f,30.f,42.f,58.f,80.f,110.f,152.f,
                            210.f,290.f,400.f,552.f,762.f,1052.f,1452.f,2004.f};

    #pragma unroll
    for (int l = 0; l < 16; l++) {
        float res = resf[l];
        float s0 = x0 * res, s1 = x1 * res, s2 = x2 * res;
        float f0 = floorf(s0), f1 = floorf(s1), f2 = floorf(s2);
        float t0 = s0 - f0, t1 = s1 - f1, t2 = s2 - f2;
        float u0 = 1.0f - t0, u1 = 1.0f - t1, u2 = 1.0f - t2;
        uint32_t i0 = (uint32_t)f0, i1 = (uint32_t)f1, i2 = (uint32_t)f2;
        const float2* tab2 = reinterpret_cast<const float2*>(tables) + (size_t)l * (size_t)THASH;
        const float4* tab4 = reinterpret_cast<const float4*>(tab2);

        uint32_t hy0 = i1 * PI2, hy1 = (i1 + 1u) * PI2;
        uint32_t hz0 = i2 * PI3, hz1 = (i2 + 1u) * PI3;
        bool even = (i0 & 1u) == 0u;

        float a0 = 0.0f, a1 = 0.0f;
        #pragma unroll
        for (int cyz = 0; cyz < 4; cyz++) {
            uint32_t hyz = ((cyz & 1) ? hy1 : hy0) ^ ((cyz & 2) ? hz1 : hz0);
            float wyz = ((cyz & 1) ? t1 : u1) * ((cyz & 2) ? t2 : u2);
            uint32_t ia = (i0 ^ hyz) & THASH_MASK;  // corner (x, cy, cz)
            float ax, ay, bx, by;
            if (even) {
                // corners x and x+1 hash to ia and ia^1 -> one aligned float4
                float4 g = __ldg(tab4 + (ia >> 1));
                bool lo = (ia & 1u) == 0u;
                ax = lo ? g.x : g.z; ay = lo ? g.y : g.w;
                bx = lo ? g.z : g.x; by = lo ? g.w : g.y;
            } else {
                uint32_t ib = ((i0 + 1u) ^ hyz) & THASH_MASK;
                float2 ga = __ldg(tab2 + ia);
                float2 gb = __ldg(tab2 + ib);
                ax = ga.x; ay = ga.y; bx = gb.x; by = gb.y;
            }
            float wa = wyz * u0, wb = wyz * t0;
            a0 = fmaf(wa, ax, fmaf(wb, bx, a0));
            a1 = fmaf(wa, ay, fmaf(wb, by, a1));
        }

        // h1 += a0 * w1[2l,:] + a1 * w1[2l+1,:]
        const int r0 = (OW1 + (2 * l) * 64) >> 2;
        const int r1 = (OW1 + (2 * l + 1) * 64) >> 2;
        #pragma unroll
        for (int j4 = 0; j4 < 16; j4++) {
            float4 u = cw4[r0 + j4];
            float4 v = cw4[r1 + j4];
            h1[4*j4+0] = fmaf(a0, u.x, fmaf(a1, v.x, h1[4*j4+0]));
            h1[4*j4+1] = fmaf(a0, u.y, fmaf(a1, v.y, h1[4*j4+1]));
            h1[4*j4+2] = fmaf(a0, u.z, fmaf(a1, v.z, h1[4*j4+2]));
            h1[4*j4+3] = fmaf(a0, u.w, fmaf(a1, v.w, h1[4*j4+3]));
        }
    }

    // ---- h2 = relu(h1) @ w2 + b2 ----
    float h2[16];
    #pragma unroll
    for (int j4 = 0; j4 < 4; j4++) {
        float4 b = cw4[(OB2 >> 2) + j4];
        h2[4*j4+0] = b.x; h2[4*j4+1] = b.y; h2[4*j4+2] = b.z; h2[4*j4+3] = b.w;
    }
    #pragma unroll
    for (int k = 0; k < 64; k++) {
        float f = fmaxf(h1[k], 0.0f);
        const int rb = (OW2 + k * 16) >> 2;
        #pragma unroll
        for (int j4 = 0; j4 < 4; j4++) {
            float4 u = cw4[rb + j4];
            h2[4*j4+0] = fmaf(f, u.x, h2[4*j4+0]);
            h2[4*j4+1] = fmaf(f, u.y, h2[4*j4+1]);
            h2[4*j4+2] = fmaf(f, u.z, h2[4*j4+2]);
            h2[4*j4+3] = fmaf(f, u.w, h2[4*j4+3]);
        }
    }

    out_sigma[n] = mask ? h2[0] : -100000.0f;

    // ---- c1 = relu(b3 + [dir(27)|h2(16)] @ w3), streamed ----
    float c1[64];
    #pragma unroll
    for (int j4 = 0; j4 < 16; j4++) {
        float4 b = cw4[(OB3 >> 2) + j4];
        c1[4*j4+0] = b.x; c1[4*j4+1] = b.y; c1[4*j4+2] = b.z; c1[4*j4+3] = b.w;
    }

    float dv[3];
    dv[0] = gd[3 * n + 0]; dv[1] = gd[3 * n + 1]; dv[2] = gd[3 * n + 2];

    #define C1_ACC(row, val) do {                                             \
        const int _rb = (OW3 + (row) * 64) >> 2;                              \
        float _f = (val);                                                     \
        _Pragma("unroll")                                                     \
        for (int j4 = 0; j4 < 16; j4++) {                                     \
            float4 u = cw4[_rb + j4];                                         \
            c1[4*j4+0] = fmaf(_f, u.x, c1[4*j4+0]);                           \
            c1[4*j4+1] = fmaf(_f, u.y, c1[4*j4+1]);                           \
            c1[4*j4+2] = fmaf(_f, u.z, c1[4*j4+2]);                           \
            c1[4*j4+3] = fmaf(_f, u.w, c1[4*j4+3]);                           \
        }                                                                     \
    } while (0)

    C1_ACC(0, dv[0]);
    C1_ACC(1, dv[1]);
    C1_ACC(2, dv[2]);
    #pragma unroll
    for (int dim = 0; dim < 3; dim++) {
        #pragma unroll
        for (int f = 0; f < 4; f++) {
            float ang = dv[dim] * (float)(1 << f);
            float s, c;
            __sincosf(ang, &s, &c);
            C1_ACC(3  + dim * 4 + f, s);
            C1_ACC(15 + dim * 4 + f, c);
        }
    }
    #pragma unroll
    for (int j = 0; j < 16; j++) C1_ACC(27 + j, h2[j]);
    #undef C1_ACC

    #pragma unroll
    for (int j = 0; j < 64; j++) c1[j] = fmaxf(c1[j], 0.0f);

    // ---- c2 = relu(c1 @ w4 + b4) in 32-wide halves, folded into col ----
    float col[3];
    {
        float4 b0 = cw4[OB5 >> 2];
        col[0] = b0.x; col[1] = b0.y; col[2] = b0.z;
    }

    #pragma unroll
    for (int half = 0; half < 2; half++) {
        float c2h[32];
        const int jbase = half * 32;
        #pragma unroll
        for (int j4 = 0; j4 < 8; j4++) {
            float4 b = cw4[((OB4 + jbase) >> 2) + j4];
            c2h[4*j4+0] = b.x; c2h[4*j4+1] = b.y; c2h[4*j4+2] = b.z; c2h[4*j4+3] = b.w;
        }
        #pragma unroll
        for (int k = 0; k < 64; k++) {
            float f = c1[k];
            const int rb = (OW4 + k * 64 + jbase) >> 2;
            #pragma unroll
            for (int j4 = 0; j4 < 8; j4++) {
                float4 u = cw4[rb + j4];
                c2h[4*j4+0] = fmaf(f, u.x, c2h[4*j4+0]);
                c2h[4*j4+1] = fmaf(f, u.y, c2h[4*j4+1]);
                c2h[4*j4+2] = fmaf(f, u.z, c2h[4*j4+2]);
                c2h[4*j4+3] = fmaf(f, u.w, c2h[4*j4+3]);
            }
        }
        #pragma unroll
        for (int k = 0; k < 32; k++) {
            float f = fmaxf(c2h[k], 0.0f);
            const int rw = OW5 + (jbase + k) * 3;
            col[0] = fmaf(f, cw[rw + 0], col[0]);
            col[1] = fmaf(f, cw[rw + 1], col[1]);
            col[2] = fmaf(f, cw[rw + 2], col[2]);
        }
    }

    #pragma unroll
    for (int j = 0; j < 3; j++) {
        float v = 1.0f / (1.0f + __expf(-col[j]));
        out_color[3 * n + j] = mask ? v : 0.0f;
    }
}

extern "C" void kernel_launch(void* const* d_in, const int* in_sizes, int n_in,
                              void* d_out, int out_size)
{
    const float* x      = (const float*)d_in[0];
    const float* d      = (const float*)d_in[1];
    const float* tables = (const float*)d_in[2];

    // copy weights into constant memory (D2D, graph-capturable)
    cudaMemcpyToSymbolAsync(cw, d_in[3],  2048 * 4, (size_t)OW1 * 4, cudaMemcpyDeviceToDevice, 0);
    cudaMemcpyToSymbolAsync(cw, d_in[4],    64 * 4, (size_t)OB1 * 4, cudaMemcpyDeviceToDevice, 0);
    cudaMemcpyToSymbolAsync(cw, d_in[5],  1024 * 4, (size_t)OW2 * 4, cudaMemcpyDeviceToDevice, 0);
    cudaMemcpyToSymbolAsync(cw, d_in[6],    16 * 4, (size_t)OB2 * 4, cudaMemcpyDeviceToDevice, 0);
    cudaMemcpyToSymbolAsync(cw, d_in[7],  2752 * 4, (size_t)OW3 * 4, cudaMemcpyDeviceToDevice, 0);
    cudaMemcpyToSymbolAsync(cw, d_in[8],    64 * 4, (size_t)OB3 * 4, cudaMemcpyDeviceToDevice, 0);
    cudaMemcpyToSymbolAsync(cw, d_in[9],  4096 * 4, (size_t)OW4 * 4, cudaMemcpyDeviceToDevice, 0);
    cudaMemcpyToSymbolAsync(cw, d_in[10],   64 * 4, (size_t)OB4 * 4, cudaMemcpyDeviceToDevice, 0);
    cudaMemcpyToSymbolAsync(cw, d_in[11],  192 * 4, (size_t)OW5 * 4, cudaMemcpyDeviceToDevice, 0);
    cudaMemcpyToSymbolAsync(cw, d_in[12],    3 * 4, (size_t)OB5 * 4, cudaMemcpyDeviceToDevice, 0);

    int N = in_sizes[0] / 3;
    float* out       = (float*)d_out;
    float* out_color = out;                   // [N,3]
    float* out_sigma = out + 3 * (size_t)N;   // [N]

    int block = 128;
    int grid  = (N + block - 1) / block;
    ngp_fused_kernel<<<grid, block>>>(x, d, tables, out_color, out_sigma, N);
}